// round 3
// baseline (speedup 1.0000x reference)
#include <cuda_runtime.h>
#include <cstdint>
#include <cstddef>

// ---------------- scratch (__device__ globals; no allocation) ----------------
__device__ float g_app[16384 * 512];
__device__ float g_motproj[1024 * 512];
__device__ float g_qproj[128 * 512];
__device__ float g_h1[1024 * 1024];
__device__ float g_objs2[1024 * 14 * 512];
__device__ float g_clip[1024 * 12 * 512];
__device__ float g_gatesx[1024 * 2048];
__device__ float g_gates[128 * 2048];
__device__ float g_hstate[128 * 512];
__device__ float g_cstate[128 * 512];
__device__ float g_vm[128 * 512];
__device__ float g_h2[1536 * 1024];
__device__ float g_objs4[128 * 6 * 12 * 512];

// ---------------- SGEMM: C = act(A @ W^T + bias), W is [N,K] row-major ------
// acc in packed f32x2 (fma.rn.f32x2). Output row offset:
//   (m/c_inner)*c_so + (m%c_inner)*c_sr.
// act: 0 none | 1 elu | 2 C *= sigmoid(v) | 3 v += add[m*add_sr+n]
template<int BM, int TM>
__global__ void __launch_bounds__(256)
sgemm_kernel(const float* __restrict__ A, int lda,
             const float* __restrict__ W,
             const float* __restrict__ bias,
             const float* __restrict__ add, long long add_sr,
             float* __restrict__ C, int c_inner, long long c_so, long long c_sr,
             int K, int act)
{
    constexpr int BN = BM, TN = TM, BK = 16;
    __shared__ __align__(16) float As[BK][BM];
    __shared__ __align__(16) float Bs[BK][BN];
    const int bm = blockIdx.y * BM, bn = blockIdx.x * BN;
    const int tid = threadIdx.x, tx = tid & 15, ty = tid >> 4;

    unsigned long long acc[TM][TN / 2];
#pragma unroll
    for (int i = 0; i < TM; i++)
#pragma unroll
        for (int j = 0; j < TN / 2; j++) acc[i][j] = 0ull;

    constexpr int NIT = (BM * BK / 4) / 256;
    for (int k0 = 0; k0 < K; k0 += BK) {
#pragma unroll
        for (int it = 0; it < NIT; it++) {
            int f = tid + 256 * it, r = f >> 2, c4 = (f & 3) << 2;
            float4 va = *(const float4*)(A + (size_t)(bm + r) * lda + k0 + c4);
            As[c4 + 0][r] = va.x; As[c4 + 1][r] = va.y;
            As[c4 + 2][r] = va.z; As[c4 + 3][r] = va.w;
            float4 vb = *(const float4*)(W + (size_t)(bn + r) * K + k0 + c4);
            Bs[c4 + 0][r] = vb.x; Bs[c4 + 1][r] = vb.y;
            Bs[c4 + 2][r] = vb.z; Bs[c4 + 3][r] = vb.w;
        }
        __syncthreads();
#pragma unroll
        for (int kk = 0; kk < BK; kk++) {
            float av[TM];
            float4 a0 = *(const float4*)(&As[kk][ty * 4]);
            av[0] = a0.x; av[1] = a0.y; av[2] = a0.z; av[3] = a0.w;
            if constexpr (TM == 8) {
                float4 a1 = *(const float4*)(&As[kk][BM / 2 + ty * 4]);
                av[4] = a1.x; av[5] = a1.y; av[6] = a1.z; av[7] = a1.w;
            }
            unsigned long long bp[TN / 2];
            double2 b0 = *(const double2*)(&Bs[kk][tx * 4]);
            bp[0] = (unsigned long long)__double_as_longlong(b0.x);
            bp[1] = (unsigned long long)__double_as_longlong(b0.y);
            if constexpr (TN == 8) {
                double2 b1 = *(const double2*)(&Bs[kk][BN / 2 + tx * 4]);
                bp[2] = (unsigned long long)__double_as_longlong(b1.x);
                bp[3] = (unsigned long long)__double_as_longlong(b1.y);
            }
#pragma unroll
            for (int i = 0; i < TM; i++) {
                unsigned long long ap;
                asm("mov.b64 %0, {%1, %1};" : "=l"(ap) : "r"(__float_as_uint(av[i])));
#pragma unroll
                for (int j = 0; j < TN / 2; j++)
                    asm("fma.rn.f32x2 %0, %1, %2, %0;"
                        : "+l"(acc[i][j]) : "l"(ap), "l"(bp[j]));
            }
        }
        __syncthreads();
    }
#pragma unroll
    for (int i = 0; i < TM; i++) {
        int mi = (TM == 8) ? ((i < 4) ? ty * 4 + i : BM / 2 + ty * 4 + (i - 4))
                           : ty * 4 + i;
        int m = bm + mi;
        size_t crow = (size_t)(m / c_inner) * (size_t)c_so
                    + (size_t)(m % c_inner) * (size_t)c_sr;
#pragma unroll
        for (int j = 0; j < TN; j++) {
            int nj = (TN == 8) ? ((j < 4) ? tx * 4 + j : BN / 2 + tx * 4 + (j - 4))
                               : tx * 4 + j;
            int n = bn + nj;
            unsigned long long p = acc[i][j >> 1];
            unsigned lane = (j & 1) ? (unsigned)(p >> 32) : (unsigned)p;
            float v = __uint_as_float(lane) + bias[n];
            float* cp = C + crow + n;
            if (act == 0)      *cp = v;
            else if (act == 1) *cp = (v > 0.f) ? v : expm1f(v);
            else if (act == 2) *cp = *cp * (1.f / (1.f + expf(-v)));
            else { v += add[(size_t)m * add_sr + n]; *cp = v; }
        }
    }
}

// out[m*out_ld + d] = mean over bits j of mask of
//   objs[(m/inner)*sB + (m%inner)*sR + j*sJ + d], D=512 (128 float4/row)
__global__ void mean_subset_kernel(float* __restrict__ out, int out_ld,
                                   const float* __restrict__ objs,
                                   int inner, long long sB, long long sR, long long sJ,
                                   unsigned mask, float inv, int M)
{
    int idx = blockIdx.x * blockDim.x + threadIdx.x;
    int m = idx >> 7, d4 = (idx & 127) << 2;
    if (m >= M) return;
    const float* base = objs + (size_t)(m / inner) * sB + (size_t)(m % inner) * sR + d4;
    float sx = 0.f, sy = 0.f, sz = 0.f, sw = 0.f;
    unsigned mm = mask;
    while (mm) {
        int j = __ffs((int)mm) - 1; mm &= mm - 1;
        float4 v = *(const float4*)(base + (size_t)j * sJ);
        sx += v.x; sy += v.y; sz += v.z; sw += v.w;
    }
    float4 o = {sx * inv, sy * inv, sz * inv, sw * inv};
    *(float4*)(out + (size_t)m * out_ld + d4) = o;
}

__global__ void fill_cond_kernel(float* __restrict__ out, int out_ld,
                                 const float* __restrict__ cond, int div, int M)
{
    int idx = blockIdx.x * blockDim.x + threadIdx.x;
    int m = idx >> 7, d4 = (idx & 127) << 2;
    if (m >= M) return;
    *(float4*)(out + (size_t)m * out_ld + d4) =
        *(const float4*)(cond + (size_t)(m / div) * 512 + d4);
}

__global__ void zero_kernel(float* p, int n)
{
    int i = blockIdx.x * blockDim.x + threadIdx.x;
    if (i < n) p[i] = 0.f;
}

__global__ void lstm_cell_kernel(const float* __restrict__ gates,
                                 float* __restrict__ h, float* __restrict__ c)
{
    int idx = blockIdx.x * blockDim.x + threadIdx.x;
    int m = idx >> 9, d = idx & 511;
    const float* gr = gates + (size_t)m * 2048;
    float ig = 1.f / (1.f + expf(-gr[d]));
    float fg = 1.f / (1.f + expf(-gr[512 + d]));
    float gg = tanhf(gr[1024 + d]);
    float og = 1.f / (1.f + expf(-gr[1536 + d]));
    float cn = fg * c[idx] + ig * gg;
    c[idx] = cn;
    h[idx] = og * tanhf(cn);
}

// ---------------- host-side exact numpy RandomState(0) replication ----------
namespace {
struct MT19937 {
    unsigned mt[624]; int pos;
    void seed(unsigned s) {
        for (int i = 0; i < 624; i++) { mt[i] = s; s = 1812433253u * (s ^ (s >> 30)) + (unsigned)i + 1u; }
        pos = 624;
    }
    unsigned next() {
        if (pos >= 624) {
            for (int i = 0; i < 624; i++) {
                unsigned y = (mt[i] & 0x80000000u) | (mt[(i + 1) % 624] & 0x7fffffffu);
                unsigned v = mt[(i + 397) % 624] ^ (y >> 1);
                if (y & 1u) v ^= 0x9908b0dfu;
                mt[i] = v;
            }
            pos = 0;
        }
        unsigned y = mt[pos++];
        y ^= y >> 11; y ^= (y << 7) & 0x9d2c5680u; y ^= (y << 15) & 0xefc60000u; y ^= y >> 18;
        return y;
    }
    unsigned interval(unsigned mx) {  // rk_interval: uniform on [0, mx]
        if (!mx) return 0;
        unsigned mask = mx;
        mask |= mask >> 1; mask |= mask >> 2; mask |= mask >> 4; mask |= mask >> 8; mask |= mask >> 16;
        unsigned v; do { v = next() & mask; } while (v > mx);
        return v;
    }
};

static int perm_first(MT19937& r, int n) {  // permutation(n)[0] via shuffle
    static int arr[13000];
    for (int i = 0; i < n; i++) arr[i] = i;
    for (int i = n - 1; i > 0; i--) {
        int j = (int)r.interval((unsigned)i);
        int t = arr[i]; arr[i] = arr[j]; arr[j] = t;
    }
    return arr[0];
}

static unsigned unrank_mask(int n, int k, long long idx, const unsigned long long Bn[17][17]) {
    unsigned mask = 0; int x = 0;
    for (int i = 0; i < k; i++)
        for (int v = x;; v++) {
            long long c = (long long)Bn[n - 1 - v][k - 1 - i];
            if (idx < c) { mask |= 1u << v; x = v + 1; break; }
            idx -= c;
        }
    return mask;
}

static void launch_gemm(bool big, const float* A, int lda, const float* W,
                        const float* bias, float* C, int c_inner,
                        long long c_so, long long c_sr,
                        int M, int N, int K, int act,
                        const float* add = nullptr, long long add_sr = 0) {
    if (big) {
        dim3 grid(N / 128, M / 128);
        sgemm_kernel<128, 8><<<grid, 256>>>(A, lda, W, bias, add, add_sr, C, c_inner, c_so, c_sr, K, act);
    } else {
        dim3 grid(N / 64, M / 64);
        sgemm_kernel<64, 4><<<grid, 256>>>(A, lda, W, bias, add, add_sr, C, c_inner, c_so, c_sr, K, act);
    }
}
}  // namespace

extern "C" void kernel_launch(void* const* d_in, const int* in_sizes, int n_in,
                              void* d_out, int out_size)
{
    (void)in_sizes; (void)n_in; (void)out_size;
    const float* app = (const float*)d_in[0];
    const float* mot = (const float*)d_in[1];
    const float* qe  = (const float*)d_in[2];
    const float* Wq  = (const float*)d_in[3];
    const float* bq  = (const float*)d_in[4];
    const float* Wm  = (const float*)d_in[5];
    const float* bmv = (const float*)d_in[6];
    const float* Wa  = (const float*)d_in[7];
    const float* ba  = (const float*)d_in[8];
    const float* Wvm = (const float*)d_in[9];
    const float* bvm = (const float*)d_in[10];
    const float* Wih = (const float*)d_in[11];
    const float* Whh = (const float*)d_in[12];
    const float* bih = (const float*)d_in[13];
    const float* bhh = (const float*)d_in[14];
    const float* W1  = (const float*)d_in[15];
    const float* b1  = (const float*)d_in[16];
    const float* W2  = (const float*)d_in[17];
    const float* b2  = (const float*)d_in[18];
    const float* gW2 = (const float*)d_in[19];
    const float* gb2 = (const float*)d_in[20];
    const float* W3  = (const float*)d_in[21];
    const float* b3  = (const float*)d_in[22];
    const float* W4  = (const float*)d_in[23];
    const float* b4  = (const float*)d_in[24];
    const float* gW4 = (const float*)d_in[25];
    const float* gb4 = (const float*)d_in[26];
    float* outp = (float*)d_out;

    // RNG: 36 choice() calls in reference trace order
    unsigned long long Bn[17][17] = {};
    for (int i = 0; i <= 16; i++) {
        Bn[i][0] = 1;
        for (int j = 1; j <= i; j++)
            Bn[i][j] = Bn[i - 1][j - 1] + ((j <= i - 1) ? Bn[i - 1][j] : 0ull);
    }
    unsigned masks[36]; float invs[36];
    {
        MT19937 rng; rng.seed(0);
        int ptr = 0;
        auto doCall = [&](int n, int steps) {
            for (int s = 0; s < steps; s++) {
                int scale = n - (s + 1);
                int pop = (int)Bn[n][scale];
                int r = perm_first(rng, pop);
                masks[ptr] = unrank_mask(n, scale, (long long)r, Bn);
                invs[ptr] = 1.0f / (float)scale;
                ptr++;
            }
        };
        doCall(16, 14); doCall(14, 12); doCall(8, 6); doCall(6, 4);
    }

    float *p_app, *p_motproj, *p_qproj, *p_h1, *p_objs2, *p_clip, *p_gatesx,
          *p_gates, *p_hst, *p_cst, *p_vm, *p_h2, *p_objs4;
    cudaGetSymbolAddress((void**)&p_app, g_app);
    cudaGetSymbolAddress((void**)&p_motproj, g_motproj);
    cudaGetSymbolAddress((void**)&p_qproj, g_qproj);
    cudaGetSymbolAddress((void**)&p_h1, g_h1);
    cudaGetSymbolAddress((void**)&p_objs2, g_objs2);
    cudaGetSymbolAddress((void**)&p_clip, g_clip);
    cudaGetSymbolAddress((void**)&p_gatesx, g_gatesx);
    cudaGetSymbolAddress((void**)&p_gates, g_gates);
    cudaGetSymbolAddress((void**)&p_hst, g_hstate);
    cudaGetSymbolAddress((void**)&p_cst, g_cstate);
    cudaGetSymbolAddress((void**)&p_vm, g_vm);
    cudaGetSymbolAddress((void**)&p_h2, g_h2);
    cudaGetSymbolAddress((void**)&p_objs4, g_objs4);

    // projections
    launch_gemm(false, qe, 512, Wq, bq, p_qproj, 128, 0, 512, 128, 512, 512, 0);
    launch_gemm(false, mot, 2048, Wm, bmv, p_motproj, 1024, 0, 512, 1024, 512, 2048, 0);
    launch_gemm(true, app, 2048, Wa, ba, p_app, 16384, 0, 512, 16384, 512, 2048, 0);
    launch_gemm(false, mot, 2048, Wih, bih, p_gatesx, 1024, 0, 2048, 1024, 2048, 2048, 0);

    // crn_m: 14 steps, objs=[1024,16,512], cond=mot_proj
    fill_cond_kernel<<<512, 256>>>(p_h1 + 512, 1024, p_motproj, 1, 1024);
    for (int s = 0; s < 14; s++) {
        int sc = s + 1;
        mean_subset_kernel<<<512, 256>>>(p_h1, 1024, p_app, 1024, 0, 16 * 512, 512,
                                         masks[s], invs[s], 1024);
        launch_gemm(false, p_h1, 1024, W1 + (size_t)sc * 512 * 1024, b1 + (size_t)sc * 512,
                    p_objs2 + (size_t)s * 512, 1024, 0, 14 * 512, 1024, 512, 1024, 1);
    }

    // crn_q: 12 gated steps, objs=[1024,14,512], cond=q_proj per (b) bcast over c
    fill_cond_kernel<<<512, 256>>>(p_h1 + 512, 1024, p_qproj, 8, 1024);
    for (int s = 0; s < 12; s++) {
        int sc = s + 1;
        mean_subset_kernel<<<512, 256>>>(p_h1, 1024, p_objs2, 1024, 0, 14 * 512, 512,
                                         masks[14 + s], invs[14 + s], 1024);
        float* Cp = p_clip + (size_t)s * 512;
        launch_gemm(false, p_h1, 1024, W2 + (size_t)sc * 512 * 1024, b2 + (size_t)sc * 512,
                    Cp, 1024, 0, 12 * 512, 1024, 512, 1024, 1);
        launch_gemm(false, p_h1, 1024, gW2 + (size_t)sc * 512 * 1024, gb2 + (size_t)sc * 512,
                    Cp, 1024, 0, 12 * 512, 1024, 512, 1024, 2);
    }

    // LSTM over motion (T=8)
    zero_kernel<<<256, 256>>>(p_hst, 128 * 512);
    zero_kernel<<<256, 256>>>(p_cst, 128 * 512);
    for (int t = 0; t < 8; t++) {
        launch_gemm(false, p_hst, 512, Whh, bhh, p_gates, 128, 0, 2048,
                    128, 2048, 512, 3, p_gatesx + (size_t)t * 2048, 8 * 2048);
        lstm_cell_kernel<<<256, 256>>>(p_gates, p_hst, p_cst);
    }
    launch_gemm(false, p_hst, 512, Wvm, bvm, p_vm, 128, 0, 512, 128, 512, 512, 0);

    // crn_vm: 6 steps, objs=clip [B,8,12,D] (object axis j), rows m=b*12+r
    fill_cond_kernel<<<768, 256>>>(p_h2 + 512, 1024, p_vm, 12, 1536);
    for (int s = 0; s < 6; s++) {
        int sc = s + 1;
        mean_subset_kernel<<<768, 256>>>(p_h2, 1024, p_clip,
                                         12, 8 * 12 * 512, 512, 12 * 512,
                                         masks[26 + s], invs[26 + s], 1536);
        launch_gemm(false, p_h2, 1024, W3 + (size_t)sc * 512 * 1024, b3 + (size_t)sc * 512,
                    p_objs4 + (size_t)s * 12 * 512, 12, 6 * 12 * 512, 512,
                    1536, 512, 1024, 1);
    }

    // crn_vq: 4 gated steps, objs4 [B,6,12,D] -> out [B,48,D]
    fill_cond_kernel<<<768, 256>>>(p_h2 + 512, 1024, p_qproj, 12, 1536);
    for (int s = 0; s < 4; s++) {
        int sc = s + 1;
        mean_subset_kernel<<<768, 256>>>(p_h2, 1024, p_objs4,
                                         12, 6 * 12 * 512, 512, 12 * 512,
                                         masks[32 + s], invs[32 + s], 1536);
        float* Cp = outp + (size_t)s * 12 * 512;
        launch_gemm(false, p_h2, 1024, W4 + (size_t)sc * 512 * 1024, b4 + (size_t)sc * 512,
                    Cp, 12, 48 * 512, 512, 1536, 512, 1024, 1);
        launch_gemm(false, p_h2, 1024, gW4 + (size_t)sc * 512 * 1024, gb4 + (size_t)sc * 512,
                    Cp, 12, 48 * 512, 512, 1536, 512, 1024, 2);
    }
}

// round 4
// speedup vs baseline: 1.5913x; 1.5913x over previous
#include <cuda_runtime.h>
#include <cstdint>
#include <cstddef>

// ---------------- scratch (__device__ globals; no allocation) ----------------
__device__ float g_app[16384 * 512];
__device__ float g_motproj[1024 * 512];
__device__ float g_qproj[128 * 512];
__device__ float g_mean[14 * 1536 * 512];   // batched mean buffers (max 14 steps)
__device__ float g_objs2[1024 * 14 * 512];
__device__ float g_clip[1024 * 12 * 512];
__device__ float g_gatesx[1024 * 2048];
__device__ float g_gates[128 * 2048];
__device__ float g_hstate[128 * 512];
__device__ float g_cstate[128 * 512];
__device__ float g_vm[128 * 512];
__device__ float g_objs4[128 * 6 * 12 * 512];

struct MaskArgs { unsigned m[14]; float inv[14]; };

// ---------------- SGEMM: C = act(A @ W^T + bias) ----------------------------
// A operand: k < 512 -> Aa[step] rows (lda), else (if Ac) Ac[(m/ac_div)*512 + k-512].
// W is [N,K] row-major. Batched over blockIdx.z with per-operand step strides.
// Output row offset: (m/c_inner)*c_so + (m%c_inner)*c_sr, plus step*C_step.
// act: 0 none | 1 elu | 2 C *= sigmoid(v) | 3 v += add[m*add_sr+n]
// Inner loop: packed fma.rn.f32x2 (2x fp32 FMA throughput on sm_103a).
template<int BM, int TM>
__global__ void __launch_bounds__(256)
sgemm_kernel(const float* __restrict__ Aa, long long Aa_step, int lda,
             const float* __restrict__ Ac, int ac_div,
             const float* __restrict__ W, long long W_step,
             const float* __restrict__ bias, long long bias_step,
             const float* __restrict__ add, long long add_sr,
             float* __restrict__ C, long long C_step,
             int c_inner, long long c_so, long long c_sr,
             int K, int act)
{
    constexpr int BN = BM, TN = TM, BK = 16;
    __shared__ __align__(16) float As[BK][BM];
    __shared__ __align__(16) float Bs[BK][BN];
    const int bm = blockIdx.y * BM, bn = blockIdx.x * BN;
    const int tid = threadIdx.x, tx = tid & 15, ty = tid >> 4;
    const int step = blockIdx.z;
    Aa += (size_t)step * Aa_step;
    W += (size_t)step * W_step;
    bias += (size_t)step * bias_step;
    C += (size_t)step * C_step;

    unsigned long long acc[TM][TN / 2];
#pragma unroll
    for (int i = 0; i < TM; i++)
#pragma unroll
        for (int j = 0; j < TN / 2; j++) acc[i][j] = 0ull;

    constexpr int NIT = (BM * BK / 4) / 256;
    for (int k0 = 0; k0 < K; k0 += BK) {
#pragma unroll
        for (int it = 0; it < NIT; it++) {
            int f = tid + 256 * it, r = f >> 2, c4 = (f & 3) << 2;
            int m = bm + r, k = k0 + c4;
            const float* ap;
            if (Ac && k >= 512) ap = Ac + (size_t)(m / ac_div) * 512 + (k - 512);
            else                ap = Aa + (size_t)m * lda + k;
            float4 va = *(const float4*)ap;
            As[c4 + 0][r] = va.x; As[c4 + 1][r] = va.y;
            As[c4 + 2][r] = va.z; As[c4 + 3][r] = va.w;
            float4 vb = *(const float4*)(W + (size_t)(bn + r) * K + k);
            Bs[c4 + 0][r] = vb.x; Bs[c4 + 1][r] = vb.y;
            Bs[c4 + 2][r] = vb.z; Bs[c4 + 3][r] = vb.w;
        }
        __syncthreads();
#pragma unroll
        for (int kk = 0; kk < BK; kk++) {
            float av[TM];
            float4 a0 = *(const float4*)(&As[kk][ty * 4]);
            av[0] = a0.x; av[1] = a0.y; av[2] = a0.z; av[3] = a0.w;
            if constexpr (TM == 8) {
                float4 a1 = *(const float4*)(&As[kk][BM / 2 + ty * 4]);
                av[4] = a1.x; av[5] = a1.y; av[6] = a1.z; av[7] = a1.w;
            }
            unsigned long long bp[TN / 2];
            double2 b0 = *(const double2*)(&Bs[kk][tx * 4]);
            bp[0] = (unsigned long long)__double_as_longlong(b0.x);
            bp[1] = (unsigned long long)__double_as_longlong(b0.y);
            if constexpr (TN == 8) {
                double2 b1 = *(const double2*)(&Bs[kk][BN / 2 + tx * 4]);
                bp[2] = (unsigned long long)__double_as_longlong(b1.x);
                bp[3] = (unsigned long long)__double_as_longlong(b1.y);
            }
#pragma unroll
            for (int i = 0; i < TM; i++) {
                unsigned long long ap2;
                asm("mov.b64 %0, {%1, %1};" : "=l"(ap2) : "r"(__float_as_uint(av[i])));
#pragma unroll
                for (int j = 0; j < TN / 2; j++)
                    asm("fma.rn.f32x2 %0, %1, %2, %0;"
                        : "+l"(acc[i][j]) : "l"(ap2), "l"(bp[j]));
            }
        }
        __syncthreads();
    }
#pragma unroll
    for (int i = 0; i < TM; i++) {
        int mi = (TM == 8) ? ((i < 4) ? ty * 4 + i : BM / 2 + ty * 4 + (i - 4))
                           : ty * 4 + i;
        int m = bm + mi;
        size_t crow = (size_t)(m / c_inner) * (size_t)c_so
                    + (size_t)(m % c_inner) * (size_t)c_sr;
#pragma unroll
        for (int j = 0; j < TN; j++) {
            int nj = (TN == 8) ? ((j < 4) ? tx * 4 + j : BN / 2 + tx * 4 + (j - 4))
                               : tx * 4 + j;
            int n = bn + nj;
            unsigned long long p = acc[i][j >> 1];
            unsigned lane = (j & 1) ? (unsigned)(p >> 32) : (unsigned)p;
            float v = __uint_as_float(lane) + bias[n];
            float* cp = C + crow + n;
            if (act == 0)      *cp = v;
            else if (act == 1) *cp = (v > 0.f) ? v : expm1f(v);
            else if (act == 2) *cp = *cp * (1.f / (1.f + expf(-v)));
            else { v += add[(size_t)m * add_sr + n]; *cp = v; }
        }
    }
}

// Batched subset-mean over blockIdx.y = step.
// out[step][m][d] = mean over bits j of ma.m[step] of
//   objs[(m/inner)*sB + (m%inner)*sR + j*sJ + d], D=512.
__global__ void mean_subset_batched(float* __restrict__ out,
                                    const float* __restrict__ objs,
                                    int inner, long long sB, long long sR, long long sJ,
                                    MaskArgs ma, int M)
{
    int step = blockIdx.y;
    int idx = blockIdx.x * blockDim.x + threadIdx.x;
    int m = idx >> 7, d4 = (idx & 127) << 2;
    if (m >= M) return;
    unsigned mm = ma.m[step];
    float inv = ma.inv[step];
    const float* base = objs + (size_t)(m / inner) * sB + (size_t)(m % inner) * sR + d4;
    float sx = 0.f, sy = 0.f, sz = 0.f, sw = 0.f;
    while (mm) {
        int j = __ffs((int)mm) - 1; mm &= mm - 1;
        float4 v = *(const float4*)(base + (size_t)j * sJ);
        sx += v.x; sy += v.y; sz += v.z; sw += v.w;
    }
    float4 o = {sx * inv, sy * inv, sz * inv, sw * inv};
    *(float4*)(out + (size_t)step * M * 512 + (size_t)m * 512 + d4) = o;
}

__global__ void zero_kernel(float* p, int n)
{
    int i = blockIdx.x * blockDim.x + threadIdx.x;
    if (i < n) p[i] = 0.f;
}

__global__ void lstm_cell_kernel(const float* __restrict__ gates,
                                 float* __restrict__ h, float* __restrict__ c)
{
    int idx = blockIdx.x * blockDim.x + threadIdx.x;
    int m = idx >> 9, d = idx & 511;
    const float* gr = gates + (size_t)m * 2048;
    float ig = 1.f / (1.f + expf(-gr[d]));
    float fg = 1.f / (1.f + expf(-gr[512 + d]));
    float gg = tanhf(gr[1024 + d]);
    float og = 1.f / (1.f + expf(-gr[1536 + d]));
    float cn = fg * c[idx] + ig * gg;
    c[idx] = cn;
    h[idx] = og * tanhf(cn);
}

// ---------------- host-side exact numpy RandomState(0) replication ----------
namespace {
struct MT19937 {
    unsigned mt[624]; int pos;
    void seed(unsigned s) {
        for (int i = 0; i < 624; i++) { mt[i] = s; s = 1812433253u * (s ^ (s >> 30)) + (unsigned)i + 1u; }
        pos = 624;
    }
    unsigned next() {
        if (pos >= 624) {
            for (int i = 0; i < 624; i++) {
                unsigned y = (mt[i] & 0x80000000u) | (mt[(i + 1) % 624] & 0x7fffffffu);
                unsigned v = mt[(i + 397) % 624] ^ (y >> 1);
                if (y & 1u) v ^= 0x9908b0dfu;
                mt[i] = v;
            }
            pos = 0;
        }
        unsigned y = mt[pos++];
        y ^= y >> 11; y ^= (y << 7) & 0x9d2c5680u; y ^= (y << 15) & 0xefc60000u; y ^= y >> 18;
        return y;
    }
    unsigned interval(unsigned mx) {
        if (!mx) return 0;
        unsigned mask = mx;
        mask |= mask >> 1; mask |= mask >> 2; mask |= mask >> 4; mask |= mask >> 8; mask |= mask >> 16;
        unsigned v; do { v = next() & mask; } while (v > mx);
        return v;
    }
};

static int perm_first(MT19937& r, int n) {
    static int arr[13000];
    for (int i = 0; i < n; i++) arr[i] = i;
    for (int i = n - 1; i > 0; i--) {
        int j = (int)r.interval((unsigned)i);
        int t = arr[i]; arr[i] = arr[j]; arr[j] = t;
    }
    return arr[0];
}

static unsigned unrank_mask(int n, int k, long long idx, const unsigned long long Bn[17][17]) {
    unsigned mask = 0; int x = 0;
    for (int i = 0; i < k; i++)
        for (int v = x;; v++) {
            long long c = (long long)Bn[n - 1 - v][k - 1 - i];
            if (idx < c) { mask |= 1u << v; x = v + 1; break; }
            idx -= c;
        }
    return mask;
}

// Generic non-batched GEMM launch (z = 1)
static void launch_gemm(bool big, const float* A, int lda, const float* W,
                        const float* bias, float* C, int c_inner,
                        long long c_so, long long c_sr,
                        int M, int N, int K, int act,
                        const float* add = nullptr, long long add_sr = 0) {
    if (big) {
        dim3 grid(N / 128, M / 128, 1);
        sgemm_kernel<128, 8><<<grid, 256>>>(A, 0, lda, nullptr, 1, W, 0, bias, 0,
                                            add, add_sr, C, 0, c_inner, c_so, c_sr, K, act);
    } else {
        dim3 grid(N / 64, M / 64, 1);
        sgemm_kernel<64, 4><<<grid, 256>>>(A, 0, lda, nullptr, 1, W, 0, bias, 0,
                                           add, add_sr, C, 0, c_inner, c_so, c_sr, K, act);
    }
}

// Batched CRN GEMM launch: A = [mean(step) | cond], K = 1024
static void launch_crn(const float* meanbuf, const float* cond, int ac_div,
                       const float* Wbank, const float* bbank,
                       float* C, long long C_step,
                       int c_inner, long long c_so, long long c_sr,
                       int M, int steps, int act) {
    dim3 grid(512 / 128, M / 128, steps);
    sgemm_kernel<128, 8><<<grid, 256>>>(
        meanbuf, (long long)M * 512, 512, cond, ac_div,
        Wbank + (size_t)512 * 1024, (long long)512 * 1024,
        bbank + 512, 512,
        nullptr, 0, C, C_step, c_inner, c_so, c_sr, 1024, act);
}
}  // namespace

extern "C" void kernel_launch(void* const* d_in, const int* in_sizes, int n_in,
                              void* d_out, int out_size)
{
    (void)in_sizes; (void)n_in; (void)out_size;
    const float* app = (const float*)d_in[0];
    const float* mot = (const float*)d_in[1];
    const float* qe  = (const float*)d_in[2];
    const float* Wq  = (const float*)d_in[3];
    const float* bq  = (const float*)d_in[4];
    const float* Wm  = (const float*)d_in[5];
    const float* bmv = (const float*)d_in[6];
    const float* Wa  = (const float*)d_in[7];
    const float* ba  = (const float*)d_in[8];
    const float* Wvm = (const float*)d_in[9];
    const float* bvm = (const float*)d_in[10];
    const float* Wih = (const float*)d_in[11];
    const float* Whh = (const float*)d_in[12];
    const float* bih = (const float*)d_in[13];
    const float* bhh = (const float*)d_in[14];
    const float* W1  = (const float*)d_in[15];
    const float* b1  = (const float*)d_in[16];
    const float* W2  = (const float*)d_in[17];
    const float* b2  = (const float*)d_in[18];
    const float* gW2 = (const float*)d_in[19];
    const float* gb2 = (const float*)d_in[20];
    const float* W3  = (const float*)d_in[21];
    const float* b3  = (const float*)d_in[22];
    const float* W4  = (const float*)d_in[23];
    const float* b4  = (const float*)d_in[24];
    const float* gW4 = (const float*)d_in[25];
    const float* gb4 = (const float*)d_in[26];
    float* outp = (float*)d_out;

    // ---- RNG: 36 choice() calls in reference trace order (verified exact) ----
    unsigned long long Bn[17][17] = {};
    for (int i = 0; i <= 16; i++) {
        Bn[i][0] = 1;
        for (int j = 1; j <= i; j++)
            Bn[i][j] = Bn[i - 1][j - 1] + ((j <= i - 1) ? Bn[i - 1][j] : 0ull);
    }
    MaskArgs ma1, ma2, ma3, ma4;
    {
        MT19937 rng; rng.seed(0);
        auto doCall = [&](int n, int steps, MaskArgs& out) {
            for (int s = 0; s < steps; s++) {
                int scale = n - (s + 1);
                int pop = (int)Bn[n][scale];
                int r = perm_first(rng, pop);
                out.m[s] = unrank_mask(n, scale, (long long)r, Bn);
                out.inv[s] = 1.0f / (float)scale;
            }
        };
        doCall(16, 14, ma1); doCall(14, 12, ma2); doCall(8, 6, ma3); doCall(6, 4, ma4);
    }

    float *p_app, *p_motproj, *p_qproj, *p_mean, *p_objs2, *p_clip, *p_gatesx,
          *p_gates, *p_hst, *p_cst, *p_vm, *p_objs4;
    cudaGetSymbolAddress((void**)&p_app, g_app);
    cudaGetSymbolAddress((void**)&p_motproj, g_motproj);
    cudaGetSymbolAddress((void**)&p_qproj, g_qproj);
    cudaGetSymbolAddress((void**)&p_mean, g_mean);
    cudaGetSymbolAddress((void**)&p_objs2, g_objs2);
    cudaGetSymbolAddress((void**)&p_clip, g_clip);
    cudaGetSymbolAddress((void**)&p_gatesx, g_gatesx);
    cudaGetSymbolAddress((void**)&p_gates, g_gates);
    cudaGetSymbolAddress((void**)&p_hst, g_hstate);
    cudaGetSymbolAddress((void**)&p_cst, g_cstate);
    cudaGetSymbolAddress((void**)&p_vm, g_vm);
    cudaGetSymbolAddress((void**)&p_objs4, g_objs4);

    // ---- projections ----
    launch_gemm(false, qe, 512, Wq, bq, p_qproj, 128, 0, 512, 128, 512, 512, 0);
    launch_gemm(false, mot, 2048, Wm, bmv, p_motproj, 1024, 0, 512, 1024, 512, 2048, 0);
    launch_gemm(true, app, 2048, Wa, ba, p_app, 16384, 0, 512, 16384, 512, 2048, 0);
    launch_gemm(true, mot, 2048, Wih, bih, p_gatesx, 1024, 0, 2048, 1024, 2048, 2048, 0);

    // ---- crn_m: 14 steps batched, objs = g_app [1024,16,512], cond = motproj ----
    mean_subset_batched<<<dim3(512, 14), 256>>>(p_mean, p_app, 1024, 0, 16 * 512, 512, ma1, 1024);
    launch_crn(p_mean, p_motproj, 1, W1, b1, p_objs2, 512, 1024, 0, 14 * 512, 1024, 14, 1);

    // ---- crn_q: 12 gated steps batched, objs = g_objs2, cond = qproj[m/8] ----
    mean_subset_batched<<<dim3(512, 12), 256>>>(p_mean, p_objs2, 1024, 0, 14 * 512, 512, ma2, 1024);
    launch_crn(p_mean, p_qproj, 8, W2, b2, p_clip, 512, 1024, 0, 12 * 512, 1024, 12, 1);
    launch_crn(p_mean, p_qproj, 8, gW2, gb2, p_clip, 512, 1024, 0, 12 * 512, 1024, 12, 2);

    // ---- LSTM over motion (T = 8) ----
    zero_kernel<<<256, 256>>>(p_hst, 128 * 512);
    zero_kernel<<<256, 256>>>(p_cst, 128 * 512);
    for (int t = 0; t < 8; t++) {
        launch_gemm(false, p_hst, 512, Whh, bhh, p_gates, 128, 0, 2048,
                    128, 2048, 512, 3, p_gatesx + (size_t)t * 2048, 8 * 2048);
        lstm_cell_kernel<<<256, 256>>>(p_gates, p_hst, p_cst);
    }
    launch_gemm(false, p_hst, 512, Wvm, bvm, p_vm, 128, 0, 512, 128, 512, 512, 0);

    // ---- crn_vm: 6 steps batched, objs = clip [B,8,12,D], cond = vm[m/12] ----
    mean_subset_batched<<<dim3(768, 6), 256>>>(p_mean, p_clip, 12, 8 * 12 * 512, 512, 12 * 512, ma3, 1536);
    launch_crn(p_mean, p_vm, 12, W3, b3, p_objs4, 12 * 512, 12, 6 * 12 * 512, 512, 1536, 6, 1);

    // ---- crn_vq: 4 gated steps batched, objs4 [B,6,12,D] -> out [B,48,D] ----
    mean_subset_batched<<<dim3(768, 4), 256>>>(p_mean, p_objs4, 12, 6 * 12 * 512, 512, 12 * 512, ma4, 1536);
    launch_crn(p_mean, p_qproj, 12, W4, b4, outp, 12 * 512, 12, 48 * 512, 512, 1536, 4, 1);
    launch_crn(p_mean, p_qproj, 12, gW4, gb4, outp, 12 * 512, 12, 48 * 512, 512, 1536, 4, 2);
}